// round 16
// baseline (speedup 1.0000x reference)
#include <cuda_runtime.h>
#include <cuda_fp16.h>
#include <cstdint>

#define NN     512
#define NMAT   8          // B*R = 2*4
#define TILE   64
#define CH     64         // c's per smem stage (fp16)
#define STRH   68         // smem row stride in halves: 136B rows, 8B-aligned, bank step 2
#define NUNITS 2048       // m(8)*ta(8)*ti(8)*cs(4); 128 c's per unit = 2 stages
#define GRID   444        // 148 SMs * 3 resident blocks

__device__ __half   g_Hn[NMAT * NN * NN]; // -P/16  (fp16)
__device__ __half   g_Hy[NMAT * NN * NN]; //  P     (fp16)
__device__ __half   g_Hp[NMAT * NN * NN]; //  P/16  (fp16)
__device__ double   g_acc;
__device__ unsigned g_unit;
__device__ unsigned g_done;

__device__ __forceinline__ float sigmoidf_(float x) {
    return 1.0f / (1.0f + __expf(-x));
}

// Pass 1: sigmoid + mask, transpose [B,N,N,R] -> 8 contiguous [N,N] fp16 matrices
// in three flavors: -P/16 (X operand), P (Y operand), P/16 (p operand).
__global__ void __launch_bounds__(256) prep_kernel(const float* __restrict__ logits,
                                                   const int* __restrict__ mask) {
    int idx = blockIdx.x * 256 + threadIdx.x;      // over B*N*N = 524288 (exact fit)
    int b   = idx >> 18;
    int rem = idx & (NN * NN - 1);
    int a   = rem >> 9;
    int i   = rem & (NN - 1);

    float4 v = reinterpret_cast<const float4*>(logits)[idx];
    float mm = ((mask[b * NN + a] > 0) && (mask[b * NN + i] > 0)) ? 1.0f : 0.0f;

    float p[4];
    p[0] = mm * sigmoidf_(v.x);
    p[1] = mm * sigmoidf_(v.y);
    p[2] = mm * sigmoidf_(v.z);
    p[3] = mm * sigmoidf_(v.w);

    int base = a * NN + i;
    int moff = b * 4 * NN * NN;
    #pragma unroll
    for (int r = 0; r < 4; ++r) {
        int o = moff + r * NN * NN + base;
        g_Hn[o] = __float2half_rn(-p[r] * 0.0625f);
        g_Hy[o] = __float2half_rn( p[r]);
        g_Hp[o] = __float2half_rn( p[r] * 0.0625f);
    }
}

__device__ __forceinline__ void unit_coords(unsigned u, int& m, int& a0, int& i0, int& c0) {
    c0 = (int)(u & 3u) * 128;
    i0 = (int)((u >> 2) & 7u) * TILE;
    a0 = (int)((u >> 5) & 7u) * TILE;
    m  = (int)(u >> 8);
}

// Stage one CH-wide fp16 slab: X rows (a0..) from g_Hn, Y rows (i0..) from g_Hy.
__device__ __forceinline__ void stage_cp(int m, int a0, int i0, int cb,
                                         __half* Xb, __half* Yb, int tid) {
    const __half* Xn = g_Hn + m * NN * NN;
    const __half* Yy = g_Hy + m * NN * NN;
    #pragma unroll
    for (int k = 0; k < 4; ++k) {
        int idx = k * 256 + tid;
        int row = idx >> 4;
        int ch8 = idx & 15;               // 8B chunk = 4 halves
        const __half* sx = Xn + (a0 + row) * NN + cb + ch8 * 4;
        const __half* sy = Yy + (i0 + row) * NN + cb + ch8 * 4;
        unsigned dx = (unsigned)__cvta_generic_to_shared(Xb + row * STRH + ch8 * 4);
        unsigned dy = (unsigned)__cvta_generic_to_shared(Yb + row * STRH + ch8 * 4);
        asm volatile("cp.async.ca.shared.global [%0], [%1], 8;\n\t"
                     "cp.async.ca.shared.global [%2], [%3], 8;"
                     :: "r"(dx), "l"(sx), "r"(dy), "l"(sy));
    }
    asm volatile("cp.async.commit_group;");
}

// Pass 2: persistent, dynamic units, continuous double buffer, fused finalize.
// unit = (m, ta, ti, c-quarter): 64x64 pairs x 128 c's (2 stages of 64).
// Per triple: relu(p/16 - (x/16)*y) fused into ONE fma.rn.relu.f16x2.
__global__ void __launch_bounds__(256, 3) trans_kernel(float* __restrict__ out) {
    __shared__ __half Xs[2][TILE * STRH];
    __shared__ __half Ys[2][TILE * STRH];
    __shared__ double red[8];
    __shared__ unsigned s_next;

    int tid = threadIdx.x;
    int tx = tid & 15, ty = tid >> 4;

    float lf = 0.0f;                     // per-thread f32 accumulator (prescaled)
    int par = 0;                         // buffer parity, flows across units

    // Prologue: fetch first unit, prefetch its stage 0.
    if (tid == 0) s_next = atomicAdd(&g_unit, 1u);
    __syncthreads();
    unsigned u = s_next;
    if (u < NUNITS) {
        int m, a0, i0, c0;
        unit_coords(u, m, a0, i0, c0);
        stage_cp(m, a0, i0, c0, Xs[0], Ys[0], tid);
    }

    while (u < NUNITS) {
        int m, a0, i0, c0;
        unit_coords(u, m, a0, i0, c0);
        const __half* __restrict__ Hp = g_Hp + m * NN * NN;

        // p operand packed as {p/16, p/16} fp16x2: 16 per thread (strided 4x4)
        unsigned p2h[16];
        #pragma unroll
        for (int ja = 0; ja < 4; ++ja)
            #pragma unroll
            for (int ji = 0; ji < 4; ++ji) {
                unsigned hv = (unsigned)__half_as_ushort(
                    Hp[(a0 + ty + 16 * ja) * NN + (i0 + tx + 16 * ji)]);
                p2h[ja * 4 + ji] = hv | (hv << 16);
            }

        unsigned un = 0xffffffffu;
        #pragma unroll
        for (int s = 0; s < 2; ++s) {
            asm volatile("cp.async.wait_group 0;" ::: "memory");
            __syncthreads();               // stage visible; other buffer free; s_next published
            if (s == 0) {
                stage_cp(m, a0, i0, c0 + CH, Xs[par ^ 1], Ys[par ^ 1], tid);
                if (tid == 0) s_next = atomicAdd(&g_unit, 1u);   // next unit id, published at s=1 barrier
            } else {
                un = s_next;
                if (un < NUNITS) {
                    int m2, a2, i2, c2;
                    unit_coords(un, m2, a2, i2, c2);
                    stage_cp(m2, a2, i2, c2, Xs[par ^ 1], Ys[par ^ 1], tid);
                }
            }

            const __half* Xb = Xs[par];
            const __half* Yb = Ys[par];

            unsigned acc16[8];             // fp16x2 window for this stage (ja-pairs combined)
            #pragma unroll
            for (int k = 0; k < 8; ++k) acc16[k] = 0u;

            #pragma unroll 8
            for (int cc4 = 0; cc4 < CH / 4; ++cc4) {   // 4 c's per step
                unsigned xlo[4], xhi[4], ylo[4], yhi[4];
                #pragma unroll
                for (int j = 0; j < 4; ++j) {
                    uint2 v = *reinterpret_cast<const uint2*>(
                        Xb + (ty + 16 * j) * STRH + cc4 * 4);
                    xlo[j] = v.x; xhi[j] = v.y;
                }
                #pragma unroll
                for (int j = 0; j < 4; ++j) {
                    uint2 v = *reinterpret_cast<const uint2*>(
                        Yb + (tx + 16 * j) * STRH + cc4 * 4);
                    ylo[j] = v.x; yhi[j] = v.y;
                }
                #pragma unroll
                for (int jp = 0; jp < 2; ++jp)
                    #pragma unroll
                    for (int ji = 0; ji < 4; ++ji) {
                        unsigned q0, q1, q2, q3;
                        asm("fma.rn.relu.f16x2 %0, %1, %2, %3;"
                            : "=r"(q0) : "r"(xlo[2 * jp]), "r"(ylo[ji]),
                              "r"(p2h[2 * jp * 4 + ji]));
                        asm("fma.rn.relu.f16x2 %0, %1, %2, %3;"
                            : "=r"(q1) : "r"(xhi[2 * jp]), "r"(yhi[ji]),
                              "r"(p2h[2 * jp * 4 + ji]));
                        asm("fma.rn.relu.f16x2 %0, %1, %2, %3;"
                            : "=r"(q2) : "r"(xlo[2 * jp + 1]), "r"(ylo[ji]),
                              "r"(p2h[(2 * jp + 1) * 4 + ji]));
                        asm("fma.rn.relu.f16x2 %0, %1, %2, %3;"
                            : "=r"(q3) : "r"(xhi[2 * jp + 1]), "r"(yhi[ji]),
                              "r"(p2h[(2 * jp + 1) * 4 + ji]));
                        asm("add.rn.f16x2 %0, %1, %2;" : "=r"(q0) : "r"(q0), "r"(q1));
                        asm("add.rn.f16x2 %0, %1, %2;" : "=r"(q2) : "r"(q2), "r"(q3));
                        asm("add.rn.f16x2 %0, %1, %2;" : "=r"(q0) : "r"(q0), "r"(q2));
                        asm("add.rn.f16x2 %0, %1, %2;"
                            : "=r"(acc16[jp * 4 + ji]) : "r"(acc16[jp * 4 + ji]), "r"(q0));
                    }
            }

            // Flush stage window: fp16 tree 8 -> 1, then to f32.
            unsigned t[4];
            #pragma unroll
            for (int k = 0; k < 4; ++k)
                asm("add.rn.f16x2 %0, %1, %2;"
                    : "=r"(t[k]) : "r"(acc16[k]), "r"(acc16[k + 4]));
            asm("add.rn.f16x2 %0, %1, %2;" : "=r"(t[0]) : "r"(t[0]), "r"(t[1]));
            asm("add.rn.f16x2 %0, %1, %2;" : "=r"(t[2]) : "r"(t[2]), "r"(t[3]));
            asm("add.rn.f16x2 %0, %1, %2;" : "=r"(t[0]) : "r"(t[0]), "r"(t[2]));
            __half2 h2 = *reinterpret_cast<__half2*>(&t[0]);
            float2 f2 = __half22float2(h2);
            lf += f2.x + f2.y;

            par ^= 1;
        }
        u = un;
    }

    // Per-thread f32 -> double once; block reduction; one atomicAdd per block.
    double local = (double)lf;
    #pragma unroll
    for (int o = 16; o; o >>= 1) local += __shfl_xor_sync(0xffffffffu, local, o);
    if ((tid & 31) == 0) red[tid >> 5] = local;
    __syncthreads();
    if (tid < 32) {
        double bsum = (tid < 8) ? red[tid] : 0.0;
        #pragma unroll
        for (int o = 4; o; o >>= 1) bsum += __shfl_xor_sync(0xffffffffu, bsum, o);
        if (tid == 0) {
            atomicAdd(&g_acc, bsum);
            __threadfence();
            unsigned d = atomicAdd(&g_done, 1u);
            if (d == GRID - 1) {               // last block: finalize + reset for replay
                // undo 1/16 prescale (x16), divide by B*R (/8)  => x2
                out[0] = (float)(g_acc * 2.0);
                g_acc  = 0.0;
                g_done = 0u;
                g_unit = 0u;
            }
        }
    }
}

extern "C" void kernel_launch(void* const* d_in, const int* in_sizes, int n_in,
                              void* d_out, int out_size) {
    const float* logits = (const float*)d_in[0];   // [2,512,512,4] fp32
    const int*   masks  = (const int*)d_in[1];     // [2,512] int32
    (void)in_sizes; (void)n_in; (void)out_size;

    prep_kernel<<<(2 * NN * NN) / 256, 256>>>(logits, masks);   // 2048 blocks
    trans_kernel<<<GRID, 256>>>((float*)d_out);                 // persistent
}